// round 1
// baseline (speedup 1.0000x reference)
#include <cuda_runtime.h>
#include <cuda_bf16.h>
#include <math.h>

// DRR raycast: out[v*W+u] = step(u,v) * sum_s trilinear(volume, p0 + ts*d)
// Inputs (metadata order): volume[256^3] f32, k_inv[1,3,3], rt_inv[1,4,4],
//                          sdd[1], affine_inv[4,4], n_samples int32
// Output: f32 [1,200,200]

#define DRR_W 200
#define DRR_H 200
#define DRR_VOL 256

__device__ __forceinline__ float fetch_vox(const float* __restrict__ vol,
                                           int x, int y, int z) {
    if ((unsigned)x < (unsigned)DRR_VOL &&
        (unsigned)y < (unsigned)DRR_VOL &&
        (unsigned)z < (unsigned)DRR_VOL) {
        return __ldg(vol + (((x << 8) + y) << 8) + z);
    }
    return 0.0f;
}

__device__ __forceinline__ float trilinear(const float* __restrict__ vol,
                                           float x, float y, float z) {
    float fx = floorf(x), fy = floorf(y), fz = floorf(z);
    int ix = (int)fx, iy = (int)fy, iz = (int)fz;
    float ax = x - fx, ay = y - fy, az = z - fz;

    float c000 = fetch_vox(vol, ix,     iy,     iz);
    float c001 = fetch_vox(vol, ix,     iy,     iz + 1);
    float c010 = fetch_vox(vol, ix,     iy + 1, iz);
    float c011 = fetch_vox(vol, ix,     iy + 1, iz + 1);
    float c100 = fetch_vox(vol, ix + 1, iy,     iz);
    float c101 = fetch_vox(vol, ix + 1, iy,     iz + 1);
    float c110 = fetch_vox(vol, ix + 1, iy + 1, iz);
    float c111 = fetch_vox(vol, ix + 1, iy + 1, iz + 1);

    float c00 = c000 + az * (c001 - c000);
    float c01 = c010 + az * (c011 - c010);
    float c10 = c100 + az * (c101 - c100);
    float c11 = c110 + az * (c111 - c110);
    float c0  = c00  + ay * (c01  - c00);
    float c1  = c10  + ay * (c11  - c10);
    return c0 + ax * (c1 - c0);
}

// One warp per pixel; lanes stride the sample axis (z-dominant ray direction
// => coalesced corner loads). Warp-reduce at the end.
__global__ __launch_bounds__(256, 8)
void drr_kernel(const float* __restrict__ vol,
                const float* __restrict__ k_inv,
                const float* __restrict__ rt_inv,
                const float* __restrict__ sdd_p,
                const float* __restrict__ aff,
                const int*   __restrict__ n_ptr,
                float* __restrict__ out) {
    int gwarp = (blockIdx.x * blockDim.x + threadIdx.x) >> 5;
    int lane  = threadIdx.x & 31;
    if (gwarp >= DRR_W * DRR_H) return;

    int u = gwarp % DRR_W;
    int v = gwarp / DRR_W;

    int   n    = *n_ptr;
    float invn = 1.0f / (float)(n - 1);
    float sdd  = __ldg(sdd_p);
    float fu = (float)u, fv = (float)v;

    // tgt_cam = k_inv @ (u, v, 1) * sdd
    float tc0 = (__ldg(k_inv + 0) * fu + __ldg(k_inv + 1) * fv + __ldg(k_inv + 2)) * sdd;
    float tc1 = (__ldg(k_inv + 3) * fu + __ldg(k_inv + 4) * fv + __ldg(k_inv + 5)) * sdd;
    float tc2 = (__ldg(k_inv + 6) * fu + __ldg(k_inv + 7) * fv + __ldg(k_inv + 8)) * sdd;

    // ray = R @ tgt_cam ; src = t  (rt_inv is 4x4 row-major)
    float ray0 = __ldg(rt_inv + 0) * tc0 + __ldg(rt_inv + 1) * tc1 + __ldg(rt_inv + 2)  * tc2;
    float ray1 = __ldg(rt_inv + 4) * tc0 + __ldg(rt_inv + 5) * tc1 + __ldg(rt_inv + 6)  * tc2;
    float ray2 = __ldg(rt_inv + 8) * tc0 + __ldg(rt_inv + 9) * tc1 + __ldg(rt_inv + 10) * tc2;
    float sx = __ldg(rt_inv + 3), sy = __ldg(rt_inv + 7), sz = __ldg(rt_inv + 11);

    float step = sqrtf(ray0 * ray0 + ray1 * ray1 + ray2 * ray2) * invn;

    // vox(s) = p0 + ts * d   (affine_inv 4x4 row-major; only top 3 rows used)
    float p0x = __ldg(aff + 0) * sx + __ldg(aff + 1) * sy + __ldg(aff + 2)  * sz + __ldg(aff + 3);
    float p0y = __ldg(aff + 4) * sx + __ldg(aff + 5) * sy + __ldg(aff + 6)  * sz + __ldg(aff + 7);
    float p0z = __ldg(aff + 8) * sx + __ldg(aff + 9) * sy + __ldg(aff + 10) * sz + __ldg(aff + 11);
    float dx  = __ldg(aff + 0) * ray0 + __ldg(aff + 1) * ray1 + __ldg(aff + 2)  * ray2;
    float dy  = __ldg(aff + 4) * ray0 + __ldg(aff + 5) * ray1 + __ldg(aff + 6)  * ray2;
    float dz  = __ldg(aff + 8) * ray0 + __ldg(aff + 9) * ray1 + __ldg(aff + 10) * ray2;

    // Conservative ts-clip to [-1, VOL] per axis (outside => exact 0 contribution).
    float lo = 0.0f, hi = 1.0f;
    {
        float p0a[3] = {p0x, p0y, p0z};
        float da[3]  = {dx, dy, dz};
        #pragma unroll
        for (int k = 0; k < 3; ++k) {
            float p = p0a[k], d = da[k];
            if (fabsf(d) < 1e-12f) {
                if (p < -1.0f || p > (float)DRR_VOL) { lo = 1.0f; hi = 0.0f; }
            } else {
                float ta = (-1.0f - p) / d;
                float tb = ((float)DRR_VOL - p) / d;
                lo = fmaxf(lo, fminf(ta, tb));
                hi = fminf(hi, fmaxf(ta, tb));
            }
        }
    }

    float acc = 0.0f;
    if (lo <= hi) {
        int s_lo = (int)floorf(lo * (float)(n - 1)) - 2;
        int s_hi = (int)ceilf(hi * (float)(n - 1)) + 2;
        if (s_lo < 0) s_lo = 0;
        if (s_hi > n - 1) s_hi = n - 1;

        for (int s = s_lo + lane; s <= s_hi; s += 32) {
            float ts = (float)s * invn;
            float x = p0x + ts * dx;
            float y = p0y + ts * dy;
            float z = p0z + ts * dz;
            acc += trilinear(vol, x, y, z);
        }
    }

    // Warp reduction
    #pragma unroll
    for (int o = 16; o > 0; o >>= 1)
        acc += __shfl_down_sync(0xFFFFFFFFu, acc, o);

    if (lane == 0) out[gwarp] = acc * step;
}

extern "C" void kernel_launch(void* const* d_in, const int* in_sizes, int n_in,
                              void* d_out, int out_size) {
    const float* vol    = (const float*)d_in[0];
    const float* k_inv  = (const float*)d_in[1];
    const float* rt_inv = (const float*)d_in[2];
    const float* sdd    = (const float*)d_in[3];
    const float* aff    = (const float*)d_in[4];
    const int*   n_ptr  = (const int*)d_in[5];
    float* out = (float*)d_out;

    int n_warps = DRR_W * DRR_H;            // one warp per pixel
    int threads = 256;                      // 8 warps per block
    int blocks  = (n_warps * 32 + threads - 1) / threads;
    drr_kernel<<<blocks, threads>>>(vol, k_inv, rt_inv, sdd, aff, n_ptr, out);
}